// round 5
// baseline (speedup 1.0000x reference)
#include <cuda_runtime.h>
#include <cuda_bf16.h>
#include <cstdint>

#define SEQ_LEN 131072
#define NN 256
#define CC 16
#define NF 100
#define ROWS 128
#define TILE 16
#define NTILES 15
#define THREADS 256

// Scratch (device globals; no runtime allocation)
__device__ float g_Wt[NN * NN];   // g_Wt[j*256 + k] = W[k][j] * mask[k][j]
__device__ int   g_bad;
__device__ int   g_c0_is_W;       // set if candidate0's bit patterns are not all in {0,1}

// Shared memory layout (bytes)
#define VALS_OFF 0            // float [256][128] = 131072
#define WSH_OFF  131072       // float [16][256]  =  16384
#define ZB_OFF   147456       // float [16][128]  =   8192
#define ACT_OFF  155648       // int   [240]      =    960
#define XCOL_OFF 156608       // int   [101]      =    404
#define SMEM_BYTES 157056

__device__ __forceinline__ bool nan_bits(float v) {
    return (__float_as_uint(v) & 0x7fffffffu) > 0x7f800000u;
}

__global__ void init_kernel() { g_bad = 0; g_c0_is_W = 0; }

// Disambiguate W (float32) vs mask (int32 in {0,1}) among the two 65536-elem inputs.
__global__ void detect_kernel(const unsigned int* __restrict__ c0) {
    int idx = blockIdx.x * blockDim.x + threadIdx.x;
    if (idx < NN * NN) {
        if (c0[idx] > 1u) atomicOr(&g_c0_is_W, 1);
    }
}

__global__ void prep_kernel(const void* __restrict__ cand0, const void* __restrict__ cand1) {
    const float* W    = g_c0_is_W ? (const float*)cand0 : (const float*)cand1;
    const int*   mask = g_c0_is_W ? (const int*)cand1   : (const int*)cand0;
    int idx = blockIdx.x * blockDim.x + threadIdx.x;   // idx = j*256 + k
    if (idx < NN * NN) {
        int j = idx >> 8;
        int k = idx & 255;
        g_Wt[idx] = (mask[k * NN + j] != 0) ? W[k * NN + j] : 0.0f;
    }
}

extern __shared__ char smem[];

__global__ void __launch_bounds__(THREADS, 1)
main_kernel(const float* __restrict__ causes, const float* __restrict__ eps,
            const int* __restrict__ act_id, const int* __restrict__ X_idx,
            const int* __restrict__ y_idx, float* __restrict__ out)
{
    float* vals  = (float*)(smem + VALS_OFF);   // vals[k*128 + r]
    float* Wsh   = (float*)(smem + WSH_OFF);    // Wsh[c*256 + k]  (cols j0..j0+15)
    float* zb    = (float*)(smem + ZB_OFF);     // zb[c*128 + r]
    int*   actsh = (int*)  (smem + ACT_OFF);
    int*   xcol  = (int*)  (smem + XCOL_OFF);

    const int tid = threadIdx.x;
    const int s0  = blockIdx.x * ROWS;

    // X_idx values are sorted in [16, 255): if stored as int64, the second
    // 32-bit word is the high half (0). Probe it to pick the element stride.
    const int xstride = (__ldg(X_idx + 1) == 0) ? 2 : 1;
    if (tid < NN - CC) actsh[tid] = act_id[tid];
    if (tid < NF)      xcol[tid]  = __ldg(X_idx + tid * xstride);
    if (tid == NF)     xcol[NF]   = __ldg(y_idx);   // low word valid for int32 or int64

    // zero vals rows CC..255
    {
        float4* v4 = (float4*)(vals + CC * ROWS);
        const int n4 = (NN - CC) * ROWS / 4;
        for (int i = tid; i < n4; i += THREADS) v4[i] = make_float4(0.f, 0.f, 0.f, 0.f);
    }
    // causes -> vals rows 0..15 (transposed: vals[node][row])
    if (tid < ROWS) {
        const float4* cp = (const float4*)(causes + (size_t)(s0 + tid) * CC);
        #pragma unroll
        for (int q = 0; q < 4; q++) {
            float4 c4 = __ldg(cp + q);
            vals[(4*q + 0) * ROWS + tid] = c4.x;
            vals[(4*q + 1) * ROWS + tid] = c4.y;
            vals[(4*q + 2) * ROWS + tid] = c4.z;
            vals[(4*q + 3) * ROWS + tid] = c4.w;
        }
    }

    const int a = tid & 31;   // rows 4a .. 4a+3
    const int b = tid >> 5;   // cols 2b, 2b+1   (b in 0..7)

    for (int t = 0; t < NTILES; t++) {
        const int j0 = CC + TILE * t;

        __syncthreads();   // prev serial writes to vals visible; Wsh/zb reusable

        // eps prefetch for serial phase (row = tid)
        float4 e40, e41, e42, e43;
        if (tid < ROWS) {
            const float4* ep = (const float4*)(eps + (size_t)(s0 + tid) * (NN - CC) + (j0 - CC));
            e40 = __ldg(ep); e41 = __ldg(ep + 1); e42 = __ldg(ep + 2); e43 = __ldg(ep + 3);
        }

        // stage W tile: Wsh[c*256 + k] = W[k][j0+c]*mask, 16 cols x 256
        {
            const float4* src = (const float4*)(g_Wt + (size_t)j0 * NN);
            float4* dst = (float4*)Wsh;
            for (int i = tid; i < TILE * NN / 4; i += THREADS) dst[i] = src[i];
        }
        __syncthreads();

        // GEMM: zb[c][r] = sum_{k<j0} vals[k][r] * W[k][j0+c]
        float a00 = 0.f, a01 = 0.f, a02 = 0.f, a03 = 0.f;  // col 2b
        float a10 = 0.f, a11 = 0.f, a12 = 0.f, a13 = 0.f;  // col 2b+1
        const float* w0p = Wsh + (2 * b) * NN;
        const float* w1p = Wsh + (2 * b + 1) * NN;
        #pragma unroll 4
        for (int k = 0; k < j0; k++) {
            float4 v = *(const float4*)(vals + k * ROWS + a * 4);
            float w0 = w0p[k];
            float w1 = w1p[k];
            a00 = fmaf(v.x, w0, a00); a01 = fmaf(v.y, w0, a01);
            a02 = fmaf(v.z, w0, a02); a03 = fmaf(v.w, w0, a03);
            a10 = fmaf(v.x, w1, a10); a11 = fmaf(v.y, w1, a11);
            a12 = fmaf(v.z, w1, a12); a13 = fmaf(v.w, w1, a13);
        }
        *(float4*)(zb + (2 * b) * ROWS + a * 4)     = make_float4(a00, a01, a02, a03);
        *(float4*)(zb + (2 * b + 1) * ROWS + a * 4) = make_float4(a10, a11, a12, a13);
        __syncthreads();

        // Serial intra-tile resolution (threads 0..127, one row each)
        if (tid < ROWS) {
            const int r = tid;
            float z[16];
            #pragma unroll
            for (int c = 0; c < 16; c++) z[c] = zb[c * ROWS + r];
            float e[16];
            *(float4*)(e + 0)  = e40; *(float4*)(e + 4)  = e41;
            *(float4*)(e + 8)  = e42; *(float4*)(e + 12) = e43;
            #pragma unroll
            for (int c = 0; c < 16; c++) {
                float zz = fmaf(0.01f, e[c], z[c]);
                int aid = actsh[j0 - CC + c];
                float v;
                if (aid == 0)      v = zz;
                else if (aid == 1) v = tanhf(zz);
                else if (aid == 2) v = (zz > 0.0f) ? zz : (zz == zz ? 0.0f : zz);  // NaN-propagating relu
                else               v = 1.0f / (1.0f + expf(-zz));
                vals[(j0 + c) * ROWS + r] = v;
                #pragma unroll
                for (int c2 = c + 1; c2 < 16; c2++) {
                    float w = Wsh[c2 * NN + (j0 + c)];
                    z[c2] = fmaf(w, v, z[c2]);
                }
            }
        }
    }
    __syncthreads();

    // Gather outputs: X = vals[:, X_idx], y = vals[:, y_idx]
    float* outX = out;
    float* outY = out + (size_t)SEQ_LEN * NF;
    bool bad = false;
    for (int i = tid; i < ROWS * NF; i += THREADS) {
        int r = i / NF;
        int f = i - r * NF;
        float v = vals[xcol[f] * ROWS + r];
        bad |= nan_bits(v);
        outX[(size_t)s0 * NF + i] = v;
    }
    if (tid < ROWS) {
        float v = vals[xcol[NF] * ROWS + tid];
        bad |= nan_bits(v);
        outY[s0 + tid] = v;
    }
    if (__syncthreads_or((int)bad) && tid == 0) atomicOr(&g_bad, 1);
}

__global__ void fixup_kernel(float* __restrict__ out) {
    if (g_bad == 0) return;
    const size_t nx = (size_t)SEQ_LEN * NF;
    const size_t total = nx + (size_t)SEQ_LEN;
    for (size_t i = (size_t)blockIdx.x * blockDim.x + threadIdx.x;
         i < total; i += (size_t)gridDim.x * blockDim.x) {
        out[i] = (i < nx) ? 0.0f : -100.0f;
    }
}

extern "C" void kernel_launch(void* const* d_in, const int* in_sizes, int n_in,
                              void* d_out, int out_size) {
    // Identify inputs by element count (robust to metadata ordering).
    const float* causes = nullptr;
    const float* eps    = nullptr;
    const int*   act    = nullptr;
    const int*   X_idx  = nullptr;
    const int*   y_idx  = nullptr;
    const void*  cand0  = nullptr;   // one of {W, mask}
    const void*  cand1  = nullptr;   // the other
    for (int i = 0; i < n_in; i++) {
        int sz = in_sizes[i];
        if      (sz == SEQ_LEN * CC)        causes = (const float*)d_in[i];
        else if (sz == SEQ_LEN * (NN - CC)) eps    = (const float*)d_in[i];
        else if (sz == NN - CC)             act    = (const int*)d_in[i];
        else if (sz == NF)                  X_idx  = (const int*)d_in[i];
        else if (sz == 1)                   y_idx  = (const int*)d_in[i];
        else if (sz == NN * NN) {
            if (!cand0) cand0 = d_in[i]; else cand1 = d_in[i];
        }
    }
    float* out = (float*)d_out;

    cudaFuncSetAttribute(main_kernel, cudaFuncAttributeMaxDynamicSharedMemorySize, SMEM_BYTES);

    init_kernel<<<1, 1>>>();
    detect_kernel<<<NN, NN>>>((const unsigned int*)cand0);
    prep_kernel<<<NN, NN>>>(cand0, cand1);
    main_kernel<<<SEQ_LEN / ROWS, THREADS, SMEM_BYTES>>>(causes, eps, act, X_idx, y_idx, out);
    fixup_kernel<<<2048, 256>>>(out);
}

// round 6
// speedup vs baseline: 1.1914x; 1.1914x over previous
#include <cuda_runtime.h>
#include <cuda_bf16.h>
#include <cstdint>

#define SEQ_LEN 131072
#define NN 256
#define CC 16
#define NF 100
#define ROWS 128
#define TILE 16
#define NTILES 15
#define THREADS 256

typedef unsigned long long ull;

// Scratch (device globals; no runtime allocation)
// g_Wdup[t][k][2c+d] = W[k][CC+16t+c]*mask, duplicated (d=0,1) for f32x2 B-operands.
__device__ float g_Wdup[NTILES * NN * 2 * TILE];
__device__ int   g_bad;
__device__ int   g_c0_is_W;

// Shared memory layout (bytes)
#define VALS_OFF 0            // float [256][128]      = 131072
#define WDUP_OFF 131072       // float [256][32] dup   =  32768
#define ZB_OFF   163840       // float [4][16][128]    =  32768
#define ACT_OFF  196608       // int [240]             =    960
#define XCOL_OFF 197568       // int [101]             =    404
#define SMEM_BYTES 197972

__device__ __forceinline__ ull ffma2(ull a, ull b, ull c) {
    ull d;
    asm("fma.rn.f32x2 %0, %1, %2, %3;" : "=l"(d) : "l"(a), "l"(b), "l"(c));
    return d;
}

__device__ __forceinline__ bool nan_bits(float v) {
    return (__float_as_uint(v) & 0x7fffffffu) > 0x7f800000u;
}

__global__ void init_kernel() { g_bad = 0; g_c0_is_W = 0; }

// Disambiguate W (float32) vs mask (int32 in {0,1}) among the two 65536-elem inputs.
__global__ void detect_kernel(const unsigned int* __restrict__ c0) {
    int idx = blockIdx.x * blockDim.x + threadIdx.x;
    if (idx < NN * NN) {
        if (c0[idx] > 1u) atomicOr(&g_c0_is_W, 1);
    }
}

// Build g_Wdup. idx enumerates (t, k, c).
__global__ void prep_kernel(const void* __restrict__ cand0, const void* __restrict__ cand1) {
    const float* W    = g_c0_is_W ? (const float*)cand0 : (const float*)cand1;
    const int*   mask = g_c0_is_W ? (const int*)cand1   : (const int*)cand0;
    int idx = blockIdx.x * blockDim.x + threadIdx.x;
    if (idx < NTILES * NN * TILE) {
        int t   = idx / (NN * TILE);
        int rem = idx - t * (NN * TILE);
        int k   = rem >> 4;
        int c   = rem & 15;
        int j   = CC + 16 * t + c;
        float w = (mask[k * NN + j] != 0) ? W[k * NN + j] : 0.0f;
        float* dst = g_Wdup + (size_t)t * (NN * 32) + k * 32 + 2 * c;
        dst[0] = w; dst[1] = w;
    }
}

extern __shared__ char smem[];

__global__ void __launch_bounds__(THREADS, 1)
main_kernel(const float* __restrict__ causes, const float* __restrict__ eps,
            const int* __restrict__ act_id, const int* __restrict__ X_idx,
            const int* __restrict__ y_idx, float* __restrict__ out)
{
    float* vals  = (float*)(smem + VALS_OFF);   // vals[k*128 + r]
    float* Wdup  = (float*)(smem + WDUP_OFF);   // Wdup[k*32 + 2c+d]  (this tile's 16 cols, dup)
    float* zb    = (float*)(smem + ZB_OFF);     // zb[(s*16+c)*128 + r]
    int*   actsh = (int*)  (smem + ACT_OFF);
    int*   xcol  = (int*)  (smem + XCOL_OFF);

    const int tid = threadIdx.x;
    const int s0  = blockIdx.x * ROWS;

    // X_idx dtype probe (int32 vs int64): values sorted in [16,255) -> if int64,
    // second 32-bit word is the zero high half.
    const int xstride = (__ldg(X_idx + 1) == 0) ? 2 : 1;
    if (tid < NN - CC) actsh[tid] = act_id[tid];
    if (tid < NF)      xcol[tid]  = __ldg(X_idx + tid * xstride);
    if (tid == NF)     xcol[NF]   = __ldg(y_idx);

    // zero vals rows CC..255
    {
        float4* v4 = (float4*)(vals + CC * ROWS);
        const int n4 = (NN - CC) * ROWS / 4;
        for (int i = tid; i < n4; i += THREADS) v4[i] = make_float4(0.f, 0.f, 0.f, 0.f);
    }
    // causes -> vals rows 0..15 (transposed: vals[node][row])
    if (tid < ROWS) {
        const float4* cp = (const float4*)(causes + (size_t)(s0 + tid) * CC);
        #pragma unroll
        for (int q = 0; q < 4; q++) {
            float4 c4 = __ldg(cp + q);
            vals[(4*q + 0) * ROWS + tid] = c4.x;
            vals[(4*q + 1) * ROWS + tid] = c4.y;
            vals[(4*q + 2) * ROWS + tid] = c4.z;
            vals[(4*q + 3) * ROWS + tid] = c4.w;
        }
    }

    const int a = tid & 31;          // rowgroup: rows 4a..4a+3
    const int b = (tid >> 5) & 1;    // colgroup: cols 8b..8b+7
    const int s = tid >> 6;          // k-split 0..3

    for (int t = 0; t < NTILES; t++) {
        const int j0 = CC + TILE * t;

        __syncthreads();   // prev serial writes to vals visible; Wdup/zb reusable

        // eps prefetch for serial phase (row = tid)
        float4 e40, e41, e42, e43;
        if (tid < ROWS) {
            const float4* ep = (const float4*)(eps + (size_t)(s0 + tid) * (NN - CC) + (j0 - CC));
            e40 = __ldg(ep); e41 = __ldg(ep + 1); e42 = __ldg(ep + 2); e43 = __ldg(ep + 3);
        }

        // stage dup-W tile: rows k < j0+16 needed (GEMM k<j0, serial k in [j0,j0+16))
        {
            const float4* src = (const float4*)(g_Wdup + (size_t)t * (NN * 32));
            float4* dst = (float4*)Wdup;
            const int n4 = (j0 + TILE) * 8;   // 32 floats per k-row = 8 float4
            for (int i = tid; i < n4; i += THREADS) dst[i] = __ldg(src + i);
        }
        __syncthreads();

        // GEMM: zb[s][c][r] partials = sum_{k in split s} vals[k][r] * W[k][j0+c]
        ull accL[8], accH[8];
        #pragma unroll
        for (int c = 0; c < 8; c++) { accL[c] = 0ull; accH[c] = 0ull; }
        const int kq  = j0 >> 2;
        const int klo = kq * s;
        const int khi = klo + kq;
        #pragma unroll 2
        for (int k = klo; k < khi; k++) {
            ulonglong2 v = *(const ulonglong2*)(vals + k * ROWS + 4 * a);
            const ulonglong2* wp = (const ulonglong2*)(Wdup + k * 32 + b * 16);
            ulonglong2 w01 = wp[0];   // dup pairs for cols 8b+0, 8b+1
            ulonglong2 w23 = wp[1];
            ulonglong2 w45 = wp[2];
            ulonglong2 w67 = wp[3];
            accL[0] = ffma2(v.x, w01.x, accL[0]); accH[0] = ffma2(v.y, w01.x, accH[0]);
            accL[1] = ffma2(v.x, w01.y, accL[1]); accH[1] = ffma2(v.y, w01.y, accH[1]);
            accL[2] = ffma2(v.x, w23.x, accL[2]); accH[2] = ffma2(v.y, w23.x, accH[2]);
            accL[3] = ffma2(v.x, w23.y, accL[3]); accH[3] = ffma2(v.y, w23.y, accH[3]);
            accL[4] = ffma2(v.x, w45.x, accL[4]); accH[4] = ffma2(v.y, w45.x, accH[4]);
            accL[5] = ffma2(v.x, w45.y, accL[5]); accH[5] = ffma2(v.y, w45.y, accH[5]);
            accL[6] = ffma2(v.x, w67.x, accL[6]); accH[6] = ffma2(v.y, w67.x, accH[6]);
            accL[7] = ffma2(v.x, w67.y, accL[7]); accH[7] = ffma2(v.y, w67.y, accH[7]);
        }
        {
            float* zcol = zb + (s * 16 + 8 * b) * ROWS + 4 * a;
            #pragma unroll
            for (int c = 0; c < 8; c++) {
                *(ull*)(zcol + c * ROWS)     = accL[c];   // rows 4a, 4a+1
                *(ull*)(zcol + c * ROWS + 2) = accH[c];   // rows 4a+2, 4a+3
            }
        }
        __syncthreads();

        // Serial intra-tile resolution (threads 0..127, one row each)
        if (tid < ROWS) {
            const int r = tid;
            float z[16];
            #pragma unroll
            for (int c = 0; c < 16; c++) {
                const float* q = zb + c * ROWS + r;
                z[c] = (q[0] + q[2048]) + (q[4096] + q[6144]);
            }
            float e[16];
            *(float4*)(e + 0)  = e40; *(float4*)(e + 4)  = e41;
            *(float4*)(e + 8)  = e42; *(float4*)(e + 12) = e43;
            #pragma unroll
            for (int c = 0; c < 16; c++) {
                float zz = fmaf(0.01f, e[c], z[c]);
                int aid = actsh[j0 - CC + c];
                float v;
                if (aid == 0)      v = zz;
                else if (aid == 1) v = tanhf(zz);
                else if (aid == 2) v = (zz > 0.0f) ? zz : (zz == zz ? 0.0f : zz);  // NaN-propagating relu
                else               v = 1.0f / (1.0f + expf(-zz));
                vals[(j0 + c) * ROWS + r] = v;
                #pragma unroll
                for (int c2 = c + 1; c2 < 16; c2++) {
                    float w = Wdup[(j0 + c) * 32 + 2 * c2];
                    z[c2] = fmaf(w, v, z[c2]);
                }
            }
        }
    }
    __syncthreads();

    // Gather outputs: X = vals[:, X_idx], y = vals[:, y_idx]
    float* outX = out;
    float* outY = out + (size_t)SEQ_LEN * NF;
    bool bad = false;
    for (int i = tid; i < ROWS * NF; i += THREADS) {
        int r = i / NF;
        int f = i - r * NF;
        float v = vals[xcol[f] * ROWS + r];
        bad |= nan_bits(v);
        outX[(size_t)s0 * NF + i] = v;
    }
    if (tid < ROWS) {
        float v = vals[xcol[NF] * ROWS + tid];
        bad |= nan_bits(v);
        outY[s0 + tid] = v;
    }
    if (__syncthreads_or((int)bad) && tid == 0) atomicOr(&g_bad, 1);
}

__global__ void fixup_kernel(float* __restrict__ out) {
    if (g_bad == 0) return;
    const size_t nx = (size_t)SEQ_LEN * NF;
    const size_t total = nx + (size_t)SEQ_LEN;
    for (size_t i = (size_t)blockIdx.x * blockDim.x + threadIdx.x;
         i < total; i += (size_t)gridDim.x * blockDim.x) {
        out[i] = (i < nx) ? 0.0f : -100.0f;
    }
}

extern "C" void kernel_launch(void* const* d_in, const int* in_sizes, int n_in,
                              void* d_out, int out_size) {
    // Identify inputs by element count (robust to metadata ordering).
    const float* causes = nullptr;
    const float* eps    = nullptr;
    const int*   act    = nullptr;
    const int*   X_idx  = nullptr;
    const int*   y_idx  = nullptr;
    const void*  cand0  = nullptr;   // one of {W, mask}
    const void*  cand1  = nullptr;   // the other
    for (int i = 0; i < n_in; i++) {
        int sz = in_sizes[i];
        if      (sz == SEQ_LEN * CC)        causes = (const float*)d_in[i];
        else if (sz == SEQ_LEN * (NN - CC)) eps    = (const float*)d_in[i];
        else if (sz == NN - CC)             act    = (const int*)d_in[i];
        else if (sz == NF)                  X_idx  = (const int*)d_in[i];
        else if (sz == 1)                   y_idx  = (const int*)d_in[i];
        else if (sz == NN * NN) {
            if (!cand0) cand0 = d_in[i]; else cand1 = d_in[i];
        }
    }
    float* out = (float*)d_out;

    cudaFuncSetAttribute(main_kernel, cudaFuncAttributeMaxDynamicSharedMemorySize, SMEM_BYTES);

    init_kernel<<<1, 1>>>();
    detect_kernel<<<NN, NN>>>((const unsigned int*)cand0);
    prep_kernel<<<(NTILES * NN * TILE + 255) / 256, 256>>>(cand0, cand1);
    main_kernel<<<SEQ_LEN / ROWS, THREADS, SMEM_BYTES>>>(causes, eps, act, X_idx, y_idx, out);
    fixup_kernel<<<2048, 256>>>(out);
}

// round 7
// speedup vs baseline: 1.3717x; 1.1513x over previous
#include <cuda_runtime.h>
#include <cuda_bf16.h>
#include <cstdint>

#define SEQ_LEN 131072
#define NN 256
#define CC 16
#define NF 100
#define ROWS 128
#define TILE 16
#define NTILES 15
#define THREADS 256

typedef unsigned long long ull;

// Scratch (device globals; no runtime allocation)
// g_W16[t][k][c] = W[k][CC+16t+c] * mask  (16 cols per tile, k-major)
__device__ float g_W16[NTILES * NN * TILE];
__device__ int   g_bad;
__device__ int   g_c0_is_W;

// Shared memory layout (bytes)
#define VALS_OFF 0            // float [256][128]   = 131072
#define WSH_OFF  131072       // float [256][16]    =  16384
#define ZB_OFF   147456       // float [8][16][128] =  65536
#define ACT_OFF  212992       // int [240]          =    960
#define XCOL_OFF 213952       // int [101]          =    404
#define SMEM_BYTES 214356

__device__ __forceinline__ ull ffma2(ull a, ull b, ull c) {
    ull d;
    asm("fma.rn.f32x2 %0, %1, %2, %3;" : "=l"(d) : "l"(a), "l"(b), "l"(c));
    return d;
}

__device__ __forceinline__ ull dup2(float w) {
    ull d;
    asm("mov.b64 %0, {%1, %1};" : "=l"(d) : "f"(w));
    return d;
}

__device__ __forceinline__ bool nan_bits(float v) {
    return (__float_as_uint(v) & 0x7fffffffu) > 0x7f800000u;
}

__global__ void init_kernel() { g_bad = 0; g_c0_is_W = 0; }

// Disambiguate W (float32) vs mask (int32 in {0,1}) among the two 65536-elem inputs.
__global__ void detect_kernel(const unsigned int* __restrict__ c0) {
    int idx = blockIdx.x * blockDim.x + threadIdx.x;
    if (idx < NN * NN) {
        if (c0[idx] > 1u) atomicOr(&g_c0_is_W, 1);
    }
}

__global__ void prep_kernel(const void* __restrict__ cand0, const void* __restrict__ cand1) {
    const float* W    = g_c0_is_W ? (const float*)cand0 : (const float*)cand1;
    const int*   mask = g_c0_is_W ? (const int*)cand1   : (const int*)cand0;
    int idx = blockIdx.x * blockDim.x + threadIdx.x;   // (t, k, c)
    if (idx < NTILES * NN * TILE) {
        int t   = idx / (NN * TILE);
        int rem = idx - t * (NN * TILE);
        int k   = rem >> 4;
        int c   = rem & 15;
        int j   = CC + 16 * t + c;
        g_W16[idx] = (mask[k * NN + j] != 0) ? W[k * NN + j] : 0.0f;
    }
}

extern __shared__ char smem[];

__global__ void __launch_bounds__(THREADS, 1)
main_kernel(const float* __restrict__ causes, const float* __restrict__ eps,
            const int* __restrict__ act_id, const int* __restrict__ X_idx,
            const int* __restrict__ y_idx, float* __restrict__ out)
{
    float* vals  = (float*)(smem + VALS_OFF);   // vals[k*128 + r]
    float* Wsh   = (float*)(smem + WSH_OFF);    // Wsh[k*16 + c]  (this tile's 16 cols)
    float* zb    = (float*)(smem + ZB_OFF);     // zb[s*2048 + c*128 + r]
    int*   actsh = (int*)  (smem + ACT_OFF);
    int*   xcol  = (int*)  (smem + XCOL_OFF);

    const int tid = threadIdx.x;
    const int s0  = blockIdx.x * ROWS;

    // X_idx dtype probe (int32 vs int64): sorted values in [16,255) -> if int64,
    // the second 32-bit word is the zero high half.
    const int xstride = (__ldg(X_idx + 1) == 0) ? 2 : 1;
    if (tid < NN - CC) actsh[tid] = act_id[tid];
    if (tid < NF)      xcol[tid]  = __ldg(X_idx + tid * xstride);
    if (tid == NF)     xcol[NF]   = __ldg(y_idx);

    // zero vals rows CC..255
    {
        float4* v4 = (float4*)(vals + CC * ROWS);
        const int n4 = (NN - CC) * ROWS / 4;
        for (int i = tid; i < n4; i += THREADS) v4[i] = make_float4(0.f, 0.f, 0.f, 0.f);
    }
    // causes -> vals rows 0..15 (transposed: vals[node][row])
    if (tid < ROWS) {
        const float4* cp = (const float4*)(causes + (size_t)(s0 + tid) * CC);
        #pragma unroll
        for (int q = 0; q < 4; q++) {
            float4 c4 = __ldg(cp + q);
            vals[(4*q + 0) * ROWS + tid] = c4.x;
            vals[(4*q + 1) * ROWS + tid] = c4.y;
            vals[(4*q + 2) * ROWS + tid] = c4.z;
            vals[(4*q + 3) * ROWS + tid] = c4.w;
        }
    }

    // Thread tiling: 8 rows (two half-groups of 4) x 8 cols, 8-way k-split.
    const int rg = tid & 15;          // rowgroup: rows 4rg..4rg+3 and 64+4rg..64+4rg+3
    const int b  = (tid >> 4) & 1;    // colgroup: cols 8b..8b+7
    const int s  = tid >> 5;          // k-split 0..7 (== warp id)
    const int rA = 4 * rg;
    const int rB = 64 + 4 * rg;

    for (int t = 0; t < NTILES; t++) {
        const int j0 = CC + TILE * t;

        __syncthreads();   // prev serial writes to vals visible; Wsh/zb reusable

        // eps prefetch for serial phase (row = tid)
        float4 e40, e41, e42, e43;
        if (tid < ROWS) {
            const float4* ep = (const float4*)(eps + (size_t)(s0 + tid) * (NN - CC) + (j0 - CC));
            e40 = __ldg(ep); e41 = __ldg(ep + 1); e42 = __ldg(ep + 2); e43 = __ldg(ep + 3);
        }

        // stage W tile: rows k < j0+16 (GEMM uses k<j0, serial uses [j0, j0+16))
        {
            const float4* src = (const float4*)(g_W16 + (size_t)t * (NN * TILE));
            float4* dst = (float4*)Wsh;
            const int n4 = (j0 + TILE) * 4;   // 16 floats per k-row = 4 float4
            for (int i = tid; i < n4; i += THREADS) dst[i] = __ldg(src + i);
        }
        __syncthreads();

        // GEMM: zb[s][c][r] = sum_{k in split s} vals[k][r] * W[k][j0+c]
        ull aA0[8], aA1[8], aB0[8], aB1[8];
        #pragma unroll
        for (int c = 0; c < 8; c++) { aA0[c]=0ull; aA1[c]=0ull; aB0[c]=0ull; aB1[c]=0ull; }
        const int kq  = j0 >> 3;
        const int klo = kq * s;
        const int khi = klo + kq;
        #pragma unroll 2
        for (int k = klo; k < khi; k++) {
            const float4* wrow = (const float4*)(Wsh + k * 16 + 8 * b);
            float4 w03 = wrow[0];
            float4 w47 = wrow[1];
            ulonglong2 vA = *(const ulonglong2*)(vals + k * ROWS + rA);
            ulonglong2 vB = *(const ulonglong2*)(vals + k * ROWS + rB);
            ull wd[8];
            wd[0]=dup2(w03.x); wd[1]=dup2(w03.y); wd[2]=dup2(w03.z); wd[3]=dup2(w03.w);
            wd[4]=dup2(w47.x); wd[5]=dup2(w47.y); wd[6]=dup2(w47.z); wd[7]=dup2(w47.w);
            #pragma unroll
            for (int c = 0; c < 8; c++) {
                aA0[c] = ffma2(vA.x, wd[c], aA0[c]);
                aA1[c] = ffma2(vA.y, wd[c], aA1[c]);
                aB0[c] = ffma2(vB.x, wd[c], aB0[c]);
                aB1[c] = ffma2(vB.y, wd[c], aB1[c]);
            }
        }
        {
            float* zcol = zb + s * 2048 + (8 * b) * ROWS;
            #pragma unroll
            for (int c = 0; c < 8; c++) {
                ulonglong2 ta; ta.x = aA0[c]; ta.y = aA1[c];
                ulonglong2 tb; tb.x = aB0[c]; tb.y = aB1[c];
                *(ulonglong2*)(zcol + c * ROWS + rA) = ta;   // rows rA..rA+3
                *(ulonglong2*)(zcol + c * ROWS + rB) = tb;   // rows rB..rB+3
            }
        }
        __syncthreads();

        // Serial intra-tile resolution (threads 0..127, one row each)
        if (tid < ROWS) {
            const int r = tid;
            float z[16];
            #pragma unroll
            for (int c = 0; c < 16; c++) {
                const float* q = zb + c * ROWS + r;
                float p0 = q[0]      + q[2048];
                float p1 = q[4096]   + q[6144];
                float p2 = q[8192]   + q[10240];
                float p3 = q[12288]  + q[14336];
                z[c] = (p0 + p1) + (p2 + p3);
            }
            float e[16];
            *(float4*)(e + 0)  = e40; *(float4*)(e + 4)  = e41;
            *(float4*)(e + 8)  = e42; *(float4*)(e + 12) = e43;
            #pragma unroll
            for (int c = 0; c < 16; c++) {
                float zz = fmaf(0.01f, e[c], z[c]);
                int aid = actsh[j0 - CC + c];
                float v;
                if (aid == 0)      v = zz;
                else if (aid == 1) v = tanhf(zz);
                else if (aid == 2) v = (zz > 0.0f) ? zz : (zz == zz ? 0.0f : zz);  // NaN-propagating relu
                else               v = 1.0f / (1.0f + __expf(-zz));
                vals[(j0 + c) * ROWS + r] = v;
                #pragma unroll
                for (int c2 = c + 1; c2 < 16; c2++) {
                    float w = Wsh[(j0 + c) * 16 + c2];
                    z[c2] = fmaf(w, v, z[c2]);
                }
            }
        }
    }
    __syncthreads();

    // Gather outputs: X = vals[:, X_idx], y = vals[:, y_idx]
    float* outX = out;
    float* outY = out + (size_t)SEQ_LEN * NF;
    bool bad = false;
    for (int i = tid; i < ROWS * NF; i += THREADS) {
        int r = i / NF;
        int f = i - r * NF;
        float v = vals[xcol[f] * ROWS + r];
        bad |= nan_bits(v);
        outX[(size_t)s0 * NF + i] = v;
    }
    if (tid < ROWS) {
        float v = vals[xcol[NF] * ROWS + tid];
        bad |= nan_bits(v);
        outY[s0 + tid] = v;
    }
    if (__syncthreads_or((int)bad) && tid == 0) atomicOr(&g_bad, 1);
}

__global__ void fixup_kernel(float* __restrict__ out) {
    if (g_bad == 0) return;
    const size_t nx = (size_t)SEQ_LEN * NF;
    const size_t total = nx + (size_t)SEQ_LEN;
    for (size_t i = (size_t)blockIdx.x * blockDim.x + threadIdx.x;
         i < total; i += (size_t)gridDim.x * blockDim.x) {
        out[i] = (i < nx) ? 0.0f : -100.0f;
    }
}

extern "C" void kernel_launch(void* const* d_in, const int* in_sizes, int n_in,
                              void* d_out, int out_size) {
    // Identify inputs by element count (robust to metadata ordering).
    const float* causes = nullptr;
    const float* eps    = nullptr;
    const int*   act    = nullptr;
    const int*   X_idx  = nullptr;
    const int*   y_idx  = nullptr;
    const void*  cand0  = nullptr;   // one of {W, mask}
    const void*  cand1  = nullptr;   // the other
    for (int i = 0; i < n_in; i++) {
        int sz = in_sizes[i];
        if      (sz == SEQ_LEN * CC)        causes = (const float*)d_in[i];
        else if (sz == SEQ_LEN * (NN - CC)) eps    = (const float*)d_in[i];
        else if (sz == NN - CC)             act    = (const int*)d_in[i];
        else if (sz == NF)                  X_idx  = (const int*)d_in[i];
        else if (sz == 1)                   y_idx  = (const int*)d_in[i];
        else if (sz == NN * NN) {
            if (!cand0) cand0 = d_in[i]; else cand1 = d_in[i];
        }
    }
    float* out = (float*)d_out;

    cudaFuncSetAttribute(main_kernel, cudaFuncAttributeMaxDynamicSharedMemorySize, SMEM_BYTES);

    init_kernel<<<1, 1>>>();
    detect_kernel<<<NN, NN>>>((const unsigned int*)cand0);
    prep_kernel<<<(NTILES * NN * TILE + 255) / 256, 256>>>(cand0, cand1);
    main_kernel<<<SEQ_LEN / ROWS, THREADS, SMEM_BYTES>>>(causes, eps, act, X_idx, y_idx, out);
    fixup_kernel<<<2048, 256>>>(out);
}

// round 8
// speedup vs baseline: 1.4126x; 1.0298x over previous
#include <cuda_runtime.h>
#include <cuda_bf16.h>
#include <cstdint>

#define SEQ_LEN 131072
#define NN 256
#define CC 16
#define NF 100
#define ROWS 64
#define TILE 16
#define NTILES 15
#define THREADS 256

typedef unsigned long long ull;

// Scratch (device globals; no runtime allocation)
// g_W16[t][k][c] = W[k][CC+16t+c] * mask  (16 cols per tile, k-major)
__device__ float g_W16[NTILES * NN * TILE];
__device__ int   g_bad;
__device__ int   g_c0_is_W;

// Shared memory layout (bytes), per CTA (2 CTAs/SM: 2 x ~97KB = 195KB)
#define VALS_OFF 0            // float [256][64]    = 65536
#define WSH_OFF  65536        // float [256][16]    = 16384
#define ZB_OFF   81920        // float [4][16][64]  = 16384
#define ACT_OFF  98304        // int [240]          =   960
#define XCOL_OFF 99264        // int [101]          =   404
#define SMEM_BYTES 99668

__device__ __forceinline__ ull ffma2(ull a, ull b, ull c) {
    ull d;
    asm("fma.rn.f32x2 %0, %1, %2, %3;" : "=l"(d) : "l"(a), "l"(b), "l"(c));
    return d;
}

__device__ __forceinline__ ull dup2(float w) {
    ull d;
    asm("mov.b64 %0, {%1, %1};" : "=l"(d) : "f"(w));
    return d;
}

__device__ __forceinline__ bool nan_bits(float v) {
    return (__float_as_uint(v) & 0x7fffffffu) > 0x7f800000u;
}

__global__ void init_kernel() { g_bad = 0; g_c0_is_W = 0; }

// Disambiguate W (float32) vs mask (int32 in {0,1}) among the two 65536-elem inputs.
__global__ void detect_kernel(const unsigned int* __restrict__ c0) {
    int idx = blockIdx.x * blockDim.x + threadIdx.x;
    if (idx < NN * NN) {
        if (c0[idx] > 1u) atomicOr(&g_c0_is_W, 1);
    }
}

__global__ void prep_kernel(const void* __restrict__ cand0, const void* __restrict__ cand1) {
    const float* W    = g_c0_is_W ? (const float*)cand0 : (const float*)cand1;
    const int*   mask = g_c0_is_W ? (const int*)cand1   : (const int*)cand0;
    int idx = blockIdx.x * blockDim.x + threadIdx.x;   // (t, k, c)
    if (idx < NTILES * NN * TILE) {
        int t   = idx / (NN * TILE);
        int rem = idx - t * (NN * TILE);
        int k   = rem >> 4;
        int c   = rem & 15;
        int j   = CC + 16 * t + c;
        g_W16[idx] = (mask[k * NN + j] != 0) ? W[k * NN + j] : 0.0f;
    }
}

extern __shared__ char smem[];

__global__ void __launch_bounds__(THREADS, 2)
main_kernel(const float* __restrict__ causes, const float* __restrict__ eps,
            const int* __restrict__ act_id, const int* __restrict__ X_idx,
            const int* __restrict__ y_idx, float* __restrict__ out)
{
    float* vals  = (float*)(smem + VALS_OFF);   // vals[k*64 + r]
    float* Wsh   = (float*)(smem + WSH_OFF);    // Wsh[k*16 + c]  (this tile's 16 cols)
    float* zb    = (float*)(smem + ZB_OFF);     // zb[s*1024 + c*64 + r]
    int*   actsh = (int*)  (smem + ACT_OFF);
    int*   xcol  = (int*)  (smem + XCOL_OFF);

    const int tid = threadIdx.x;
    const int s0  = blockIdx.x * ROWS;

    // X_idx dtype probe (int32 vs int64): sorted values in [16,255) -> if int64,
    // the second 32-bit word is the zero high half.
    const int xstride = (__ldg(X_idx + 1) == 0) ? 2 : 1;
    if (tid < NN - CC) actsh[tid] = act_id[tid];
    if (tid < NF)      xcol[tid]  = __ldg(X_idx + tid * xstride);
    if (tid == NF)     xcol[NF]   = __ldg(y_idx);

    // zero vals rows CC..255
    {
        float4* v4 = (float4*)(vals + CC * ROWS);
        const int n4 = (NN - CC) * ROWS / 4;
        for (int i = tid; i < n4; i += THREADS) v4[i] = make_float4(0.f, 0.f, 0.f, 0.f);
    }
    // causes -> vals rows 0..15 (transposed: vals[node][row])
    if (tid < ROWS) {
        const float4* cp = (const float4*)(causes + (size_t)(s0 + tid) * CC);
        #pragma unroll
        for (int q = 0; q < 4; q++) {
            float4 c4 = __ldg(cp + q);
            vals[(4*q + 0) * ROWS + tid] = c4.x;
            vals[(4*q + 1) * ROWS + tid] = c4.y;
            vals[(4*q + 2) * ROWS + tid] = c4.z;
            vals[(4*q + 3) * ROWS + tid] = c4.w;
        }
    }

    // GEMM tiling: warp w -> (k-split s = w>>1, col-half b = w&1);
    // lane -> (rowgroup rg = lane&15 -> rows 4rg..4rg+3, col-quarter ch = lane>>4).
    // Each thread: 4 rows x 4 cols.
    const int lane  = tid & 31;
    const int w     = tid >> 5;
    const int s     = w >> 1;
    const int b     = w & 1;
    const int rg    = lane & 15;
    const int ch    = lane >> 4;
    const int cbase = 8 * b + 4 * ch;

    for (int t = 0; t < NTILES; t++) {
        const int j0 = CC + TILE * t;

        __syncthreads();   // prev serial writes to vals visible; Wsh/zb reusable

        // eps prefetch for serial phase (row = tid)
        float4 e40, e41, e42, e43;
        if (tid < ROWS) {
            const float4* ep = (const float4*)(eps + (size_t)(s0 + tid) * (NN - CC) + (j0 - CC));
            e40 = __ldg(ep); e41 = __ldg(ep + 1); e42 = __ldg(ep + 2); e43 = __ldg(ep + 3);
        }

        // stage W tile: rows k < j0+16 (GEMM uses k<j0, serial uses [j0, j0+16))
        {
            const float4* src = (const float4*)(g_W16 + (size_t)t * (NN * TILE));
            float4* dst = (float4*)Wsh;
            const int n4 = (j0 + TILE) * 4;   // 16 floats per k-row = 4 float4
            for (int i = tid; i < n4; i += THREADS) dst[i] = __ldg(src + i);
        }
        __syncthreads();

        // GEMM: zb[s][c][r] = sum_{k in split s} vals[k][r] * W[k][j0+c]
        ull ax[4], ay[4];
        #pragma unroll
        for (int c = 0; c < 4; c++) { ax[c] = 0ull; ay[c] = 0ull; }
        const int kq  = j0 >> 2;
        const int klo = kq * s;
        const int khi = klo + kq;
        #pragma unroll 4
        for (int k = klo; k < khi; k++) {
            ulonglong2 v = *(const ulonglong2*)(vals + k * ROWS + 4 * rg);
            float4 wv = *(const float4*)(Wsh + k * 16 + cbase);
            ull w0 = dup2(wv.x), w1 = dup2(wv.y), w2 = dup2(wv.z), w3 = dup2(wv.w);
            ax[0] = ffma2(v.x, w0, ax[0]); ay[0] = ffma2(v.y, w0, ay[0]);
            ax[1] = ffma2(v.x, w1, ax[1]); ay[1] = ffma2(v.y, w1, ay[1]);
            ax[2] = ffma2(v.x, w2, ax[2]); ay[2] = ffma2(v.y, w2, ay[2]);
            ax[3] = ffma2(v.x, w3, ax[3]); ay[3] = ffma2(v.y, w3, ay[3]);
        }
        {
            float* zbase = zb + s * 1024 + cbase * ROWS + 4 * rg;
            #pragma unroll
            for (int c = 0; c < 4; c++) {
                ulonglong2 tv; tv.x = ax[c]; tv.y = ay[c];
                *(ulonglong2*)(zbase + c * ROWS) = tv;   // rows 4rg..4rg+3 of col cbase+c
            }
        }
        __syncthreads();

        // Serial intra-tile resolution (threads 0..63, one row each)
        if (tid < ROWS) {
            const int r = tid;
            float z[16];
            #pragma unroll
            for (int c = 0; c < 16; c++) {
                const float* q = zb + c * ROWS + r;
                z[c] = (q[0] + q[1024]) + (q[2048] + q[3072]);
            }
            float e[16];
            *(float4*)(e + 0)  = e40; *(float4*)(e + 4)  = e41;
            *(float4*)(e + 8)  = e42; *(float4*)(e + 12) = e43;
            #pragma unroll
            for (int c = 0; c < 16; c++) {
                float zz = fmaf(0.01f, e[c], z[c]);
                int aid = actsh[j0 - CC + c];
                float v;
                if (aid == 0)      v = zz;
                else if (aid == 1) v = tanhf(zz);
                else if (aid == 2) v = (zz > 0.0f) ? zz : (zz == zz ? 0.0f : zz);  // NaN-propagating relu
                else               v = 1.0f / (1.0f + __expf(-zz));
                vals[(j0 + c) * ROWS + r] = v;
                #pragma unroll
                for (int c2 = c + 1; c2 < 16; c2++) {
                    float wv2 = Wsh[(j0 + c) * 16 + c2];
                    z[c2] = fmaf(wv2, v, z[c2]);
                }
            }
        }
    }
    __syncthreads();

    // Gather outputs: X = vals[:, X_idx], y = vals[:, y_idx]
    float* outX = out;
    float* outY = out + (size_t)SEQ_LEN * NF;
    bool bad = false;
    for (int i = tid; i < ROWS * NF; i += THREADS) {
        int r = i / NF;
        int f = i - r * NF;
        float v = vals[xcol[f] * ROWS + r];
        bad |= nan_bits(v);
        outX[(size_t)s0 * NF + i] = v;
    }
    if (tid < ROWS) {
        float v = vals[xcol[NF] * ROWS + tid];
        bad |= nan_bits(v);
        outY[s0 + tid] = v;
    }
    if (__syncthreads_or((int)bad) && tid == 0) atomicOr(&g_bad, 1);
}

__global__ void fixup_kernel(float* __restrict__ out) {
    if (g_bad == 0) return;
    const size_t nx = (size_t)SEQ_LEN * NF;
    const size_t total = nx + (size_t)SEQ_LEN;
    for (size_t i = (size_t)blockIdx.x * blockDim.x + threadIdx.x;
         i < total; i += (size_t)gridDim.x * blockDim.x) {
        out[i] = (i < nx) ? 0.0f : -100.0f;
    }
}

extern "C" void kernel_launch(void* const* d_in, const int* in_sizes, int n_in,
                              void* d_out, int out_size) {
    // Identify inputs by element count (robust to metadata ordering).
    const float* causes = nullptr;
    const float* eps    = nullptr;
    const int*   act    = nullptr;
    const int*   X_idx  = nullptr;
    const int*   y_idx  = nullptr;
    const void*  cand0  = nullptr;   // one of {W, mask}
    const void*  cand1  = nullptr;   // the other
    for (int i = 0; i < n_in; i++) {
        int sz = in_sizes[i];
        if      (sz == SEQ_LEN * CC)        causes = (const float*)d_in[i];
        else if (sz == SEQ_LEN * (NN - CC)) eps    = (const float*)d_in[i];
        else if (sz == NN - CC)             act    = (const int*)d_in[i];
        else if (sz == NF)                  X_idx  = (const int*)d_in[i];
        else if (sz == 1)                   y_idx  = (const int*)d_in[i];
        else if (sz == NN * NN) {
            if (!cand0) cand0 = d_in[i]; else cand1 = d_in[i];
        }
    }
    float* out = (float*)d_out;

    cudaFuncSetAttribute(main_kernel, cudaFuncAttributeMaxDynamicSharedMemorySize, SMEM_BYTES);

    init_kernel<<<1, 1>>>();
    detect_kernel<<<NN, NN>>>((const unsigned int*)cand0);
    prep_kernel<<<(NTILES * NN * TILE + 255) / 256, 256>>>(cand0, cand1);
    main_kernel<<<SEQ_LEN / ROWS, THREADS, SMEM_BYTES>>>(causes, eps, act, X_idx, y_idx, out);
    fixup_kernel<<<2048, 256>>>(out);
}